// round 5
// baseline (speedup 1.0000x reference)
#include <cuda_runtime.h>
#include <cuda_bf16.h>
#include <cstdint>

#define B_  4
#define N_  4096
#define M1_ 2048
#define M2_ 512
#define F1_ 64
#define F2_ 128
#define F3_ 1024
#define LF_ 64
#define MAXNBR 128

// ---------------- device scratch ----------------
__device__ float g_p1  [B_ * N_  * F1_];
__device__ float g_h1  [B_ * M1_ * F1_];
__device__ float g_ctr1[B_ * M1_ * 2];
__device__ float g_p2  [B_ * M1_ * F2_];
__device__ float g_h2  [B_ * M2_ * F2_];
__device__ float g_ctr2[B_ * M2_ * 2];
__device__ float g_pmax[B_ * 8 * F3_];

// ---------------- kernel: lf = tanh(tanh(x W1 + b1) W2 + b2) ----------
__global__ void lf_kernel(const float* __restrict__ x,
                          const float* __restrict__ W1, const float* __restrict__ b1,
                          const float* __restrict__ W2, const float* __restrict__ b2,
                          float* __restrict__ lf_out) {
    __shared__ float sW2[64 * 64];
    __shared__ float sW1[2 * 64];
    __shared__ float sb1[64], sb2[64];
    __shared__ float st1[64];
    int tid = threadIdx.x;
    for (int i = tid; i < 64 * 64; i += 64) sW2[i] = W2[i];
    sW1[tid] = W1[tid]; sW1[64 + tid] = W1[64 + tid];
    sb1[tid] = b1[tid]; sb2[tid] = b2[tid];
    __syncthreads();
    int row0 = blockIdx.x * 32;
    for (int r = 0; r < 32; r++) {
        int row = row0 + r;
        float x0 = x[row * 2], x1 = x[row * 2 + 1];
        float t1 = tanhf(x0 * sW1[tid] + x1 * sW1[64 + tid] + sb1[tid]);
        st1[tid] = t1;
        __syncthreads();
        float acc = sb2[tid];
#pragma unroll
        for (int c = 0; c < 64; c++) acc = fmaf(st1[c], sW2[c * 64 + tid], acc);
        lf_out[row * 64 + tid] = tanhf(acc);
        __syncthreads();
    }
}

// ---------------- p1[j] = [lf_j, zone_j] @ c1W[:65] + c1b ------
__global__ void p1_kernel(const float* __restrict__ lf, const float* __restrict__ zones,
                          const float* __restrict__ c1W, const float* __restrict__ c1b) {
    __shared__ float sW[65 * 64];
    __shared__ float sb[64];
    __shared__ float srow[64];
    int tid = threadIdx.x;  // 64
    for (int i = tid; i < 65 * 64; i += 64) sW[i] = c1W[i];
    sb[tid] = c1b[tid];
    __syncthreads();
    int row0 = blockIdx.x * 32;
    for (int r = 0; r < 32; r++) {
        int row = row0 + r;
        srow[tid] = lf[row * 64 + tid];
        __syncthreads();
        float z = zones[row];
        float acc = fmaf(z, sW[64 * 64 + tid], sb[tid]);
#pragma unroll
        for (int c = 0; c < 64; c++) acc = fmaf(srow[c], sW[c * 64 + tid], acc);
        g_p1[row * 64 + tid] = acc;
        __syncthreads();
    }
}

// ---------------- FPS: bucketed + warp bbox prune + packed atomic merge ---
// Cross-warp winner via atomicMax on packed u64 (valbits<<32 | (~idx)):
// 64-bit max == (max value, then MIN original index) -> identical to
// jnp.argmax first-occurrence. Skipped warps contribute their exact cached
// tuple (skip is provably a no-op on their md values). 4-slot ring for the
// best-cell so reset is >=2 barriers away from any reader/writer.
template <int T, int P, int N, int M, int LEVEL>
__global__ __launch_bounds__(T, 1) void fps_kernel(const float* __restrict__ pos_in) {
    const unsigned FULL = 0xFFFFFFFFu;
    int b = blockIdx.x;
    int tid = threadIdx.x;
    int lane = tid & 31;
    const float2* p = (LEVEL == 0) ? (const float2*)(pos_in + (size_t)b * N * 2)
                                   : (const float2*)(g_ctr1 + (size_t)b * N * 2);
    float* cout = (LEVEL == 0) ? (g_ctr1 + (size_t)b * M * 2)
                               : (g_ctr2 + (size_t)b * M * 2);

    __shared__ float2 sxy[N];               // ORIGINAL order (winner lookup)
    __shared__ float spx[N], spy[N];        // sorted (init only)
    __shared__ unsigned short ssidx[N];     // sorted -> original idx
    __shared__ int counts[256], offs[256], cursor[256];
    __shared__ unsigned long long sbest[4];

    // ---- load raw, publish original-order table ----
    float rx[P], ry[P];
    int cid[P];
#pragma unroll
    for (int k = 0; k < P; k++) {
        float2 v = p[tid + k * T];
        rx[k] = v.x; ry[k] = v.y;
        sxy[tid + k * T] = v;
    }
    if (tid < 256) counts[tid] = 0;
    if (tid < 4) sbest[tid] = 0ull;
    __syncthreads();
#pragma unroll
    for (int k = 0; k < P; k++) {
        int cx = (int)fminf(fmaxf((rx[k] + 18.f) * (16.f / 36.f), 0.f), 15.f);
        int cy = (int)fminf(fmaxf((ry[k] + 18.f) * (16.f / 36.f), 0.f), 15.f);
        cid[k] = cy * 16 + cx;
        atomicAdd(&counts[cid[k]], 1);
    }
    __syncthreads();
    if (tid < 256) offs[tid] = counts[tid];
    __syncthreads();
    for (int d = 1; d < 256; d <<= 1) {
        int v = 0;
        if (tid < 256 && tid >= d) v = offs[tid - d];
        __syncthreads();
        if (tid < 256 && tid >= d) offs[tid] += v;
        __syncthreads();
    }
    if (tid < 256) cursor[tid] = offs[tid] - counts[tid];
    __syncthreads();
#pragma unroll
    for (int k = 0; k < P; k++) {
        int pos = atomicAdd(&cursor[cid[k]], 1);
        spx[pos] = rx[k]; spy[pos] = ry[k];
        ssidx[pos] = (unsigned short)(tid + k * T);
    }
    __syncthreads();

    // ---- registers: my sorted segment + warp bbox ----
    float px[P], py[P], md[P];
    unsigned sidx[P];
    float bx0 = 1e30f, bx1 = -1e30f, by0 = 1e30f, by1 = -1e30f;
    int base = tid * P;
#pragma unroll
    for (int k = 0; k < P; k++) {
        px[k] = spx[base + k]; py[k] = spy[base + k];
        sidx[k] = (unsigned)ssidx[base + k];
        md[k] = 1e10f;
        bx0 = fminf(bx0, px[k]); bx1 = fmaxf(bx1, px[k]);
        by0 = fminf(by0, py[k]); by1 = fmaxf(by1, py[k]);
    }
#pragma unroll
    for (int o = 16; o > 0; o >>= 1) {
        bx0 = fminf(bx0, __shfl_xor_sync(FULL, bx0, o));
        bx1 = fmaxf(bx1, __shfl_xor_sync(FULL, bx1, o));
        by0 = fminf(by0, __shfl_xor_sync(FULL, by0, o));
        by1 = fmaxf(by1, __shfl_xor_sync(FULL, by1, o));
    }
    __syncthreads();

    float2 c0 = sxy[0];
    float lx = c0.x, ly = c0.y;
    if (tid == 0) { cout[0] = lx; cout[1] = ly; }

    float wvf = 1e10f;                    // cached warp max (uniform in warp)
    unsigned long long wpack = 0ull;      // cached packed warp tuple

    for (int t = 1; t < M; t++) {
        float ex = fmaxf(fmaxf(bx0 - lx, lx - bx1), 0.f);
        float ey = fmaxf(fmaxf(by0 - ly, ly - by1), 0.f);
        float lb = fmaf(ex, ex, ey * ey);
        if (lb < wvf) {   // uniform per-warp branch (no divergence)
            float tb = -1.f;
#pragma unroll
            for (int k = 0; k < P; k++) {
                float dx = px[k] - lx, dy = py[k] - ly;
                float d2 = fmaf(dx, dx, dy * dy);
                md[k] = fminf(md[k], d2);
                tb = fmaxf(tb, md[k]);
            }
            unsigned bi = 0xFFFFFFFFu;
#pragma unroll
            for (int k = 0; k < P; k++)
                if (md[k] == tb && sidx[k] < bi) bi = sidx[k];
            unsigned vb = __float_as_uint(tb);
            unsigned wm = __reduce_max_sync(FULL, vb);
            unsigned cand = (vb == wm) ? bi : 0xFFFFFFFFu;
            unsigned wi = __reduce_min_sync(FULL, cand);
            wvf = __uint_as_float(wm);
            wpack = ((unsigned long long)wm << 32) | (unsigned long long)(0xFFFFFFFFu - wi);
        }
        if (lane == 0) atomicMax(&sbest[t & 3], wpack);
        if (tid == 0) sbest[(t + 2) & 3] = 0ull;   // slot reused at t+4; readers done at t-2
        __syncthreads();
        unsigned long long e = sbest[t & 3];
        unsigned gi = 0xFFFFFFFFu - (unsigned)e;
        float2 w = sxy[gi];          // broadcast LDS.64
        lx = w.x; ly = w.y;
        if (tid == 0) { cout[t * 2] = lx; cout[t * 2 + 1] = ly; }
    }
}

// ---------------- SA1: radius scan + max-aggregate ------------------------
__global__ void sa1_kernel(const float* __restrict__ x, const float* __restrict__ c1W) {
    const int N = N_, M = M1_, F = F1_;
    int i = blockIdx.x, b = blockIdx.y, tid = threadIdx.x;  // 128 threads
    __shared__ float sdx[MAXNBR], sdy[MAXNBR];
    __shared__ int   snb[MAXNBR];
    __shared__ int   scnt;
    if (tid == 0) scnt = 0;
    __syncthreads();
    float cx = g_ctr1[(b * M + i) * 2], cy = g_ctr1[(b * M + i) * 2 + 1];
    const float2* pos = (const float2*)(x + (size_t)b * N * 2);
    for (int j = tid; j < N; j += 128) {
        float2 pj = pos[j];
        float dx = pj.x - cx, dy = pj.y - cy;
        float d2 = fmaf(dx, dx, dy * dy);
        if (d2 <= 0.25f) {
            int s = atomicAdd(&scnt, 1);
            if (s < MAXNBR) { snb[s] = j; sdx[s] = dx; sdy[s] = dy; }
        }
    }
    __syncthreads();
    if (tid >= F) return;
    int cnt = min(scnt, MAXNBR);
    float wx = c1W[65 * 64 + tid];
    float wy = c1W[66 * 64 + tid];
    float mx = -1e9f;
    const float* pb = g_p1 + (size_t)b * N * F;
    int n = 0;
    for (; n + 4 <= cnt; n += 4) {
        float v0 = pb[snb[n] * F + tid];
        float v1 = pb[snb[n + 1] * F + tid];
        float v2 = pb[snb[n + 2] * F + tid];
        float v3 = pb[snb[n + 3] * F + tid];
        float m0 = fmaf(sdx[n], wx, fmaf(sdy[n], wy, v0));
        float m1 = fmaf(sdx[n + 1], wx, fmaf(sdy[n + 1], wy, v1));
        float m2 = fmaf(sdx[n + 2], wx, fmaf(sdy[n + 2], wy, v2));
        float m3 = fmaf(sdx[n + 3], wx, fmaf(sdy[n + 3], wy, v3));
        mx = fmaxf(mx, fmaxf(fmaxf(m0, m1), fmaxf(m2, m3)));
    }
    for (; n < cnt; n++) {
        float m = fmaf(sdx[n], wx, fmaf(sdy[n], wy, pb[snb[n] * F + tid]));
        mx = fmaxf(mx, m);
    }
    g_h1[((size_t)b * M + i) * F + tid] = mx;
}

// ---------------- p2[j] = h1_j @ c2W[:64] + c2b ---------------------------
__global__ void p2_kernel(const float* __restrict__ c2W, const float* __restrict__ c2b) {
    __shared__ float sW[64 * 128];
    __shared__ float sb[128];
    __shared__ float srow[64];
    int tid = threadIdx.x;  // 128
    for (int i = tid; i < 64 * 128; i += 128) sW[i] = c2W[i];
    sb[tid] = c2b[tid];
    __syncthreads();
    int row0 = blockIdx.x * 32;
    for (int r = 0; r < 32; r++) {
        int row = row0 + r;
        if (tid < 64) srow[tid] = g_h1[row * 64 + tid];
        __syncthreads();
        float acc = sb[tid];
#pragma unroll
        for (int c = 0; c < 64; c++) acc = fmaf(srow[c], sW[c * 128 + tid], acc);
        g_p2[row * 128 + tid] = acc;
        __syncthreads();
    }
}

// ---------------- SA2 -----------------------------------------------------
__global__ void sa2_kernel(const float* __restrict__ c2W) {
    const int N = M1_, M = M2_, F = F2_;
    int i = blockIdx.x, b = blockIdx.y, tid = threadIdx.x;  // 128
    __shared__ float sdx[MAXNBR], sdy[MAXNBR];
    __shared__ int   snb[MAXNBR];
    __shared__ int   scnt;
    if (tid == 0) scnt = 0;
    __syncthreads();
    float cx = g_ctr2[(b * M + i) * 2], cy = g_ctr2[(b * M + i) * 2 + 1];
    const float2* pos = (const float2*)(g_ctr1 + (size_t)b * N * 2);
    for (int j = tid; j < N; j += F) {
        float2 pj = pos[j];
        float dx = pj.x - cx, dy = pj.y - cy;
        float d2 = fmaf(dx, dx, dy * dy);
        if (d2 <= 1.0f) {
            int s = atomicAdd(&scnt, 1);
            if (s < MAXNBR) { snb[s] = j; sdx[s] = dx; sdy[s] = dy; }
        }
    }
    __syncthreads();
    int cnt = min(scnt, MAXNBR);
    float wx = c2W[64 * 128 + tid];
    float wy = c2W[65 * 128 + tid];
    float mx = -1e9f;
    const float* pb = g_p2 + (size_t)b * N * F;
    int n = 0;
    for (; n + 4 <= cnt; n += 4) {
        float v0 = pb[snb[n] * F + tid];
        float v1 = pb[snb[n + 1] * F + tid];
        float v2 = pb[snb[n + 2] * F + tid];
        float v3 = pb[snb[n + 3] * F + tid];
        float m0 = fmaf(sdx[n], wx, fmaf(sdy[n], wy, v0));
        float m1 = fmaf(sdx[n + 1], wx, fmaf(sdy[n + 1], wy, v1));
        float m2 = fmaf(sdx[n + 2], wx, fmaf(sdy[n + 2], wy, v2));
        float m3 = fmaf(sdx[n + 3], wx, fmaf(sdy[n + 3], wy, v3));
        mx = fmaxf(mx, fmaxf(fmaxf(m0, m1), fmaxf(m2, m3)));
    }
    for (; n < cnt; n++) {
        float m = fmaf(sdx[n], wx, fmaf(sdy[n], wy, pb[snb[n] * F + tid]));
        mx = fmaxf(mx, m);
    }
    g_h2[((size_t)b * M + i) * F + tid] = mx;
}

// ---------------- final projection + partial max pool ---------------------
__global__ void final_partial(const float* __restrict__ W, const float* __restrict__ bias) {
    int fchunk = blockIdx.x, rchunk = blockIdx.y, b = blockIdx.z;
    int tid = threadIdx.x;  // 128
    int f = fchunk * 128 + tid;
    __shared__ float sh[64][132];
    int r0 = rchunk * 64;
    for (int e = tid; e < 64 * 130; e += 128) {
        int r = e / 130, c = e % 130;
        float v;
        if (c < 128) v = g_h2[((size_t)b * M2_ + r0 + r) * 128 + c];
        else         v = g_ctr2[(b * M2_ + r0 + r) * 2 + (c - 128)];
        sh[r][c] = v;
    }
    __syncthreads();
    float acc[64];
#pragma unroll
    for (int r = 0; r < 64; r++) acc[r] = 0.0f;
    for (int c = 0; c < 130; c++) {
        float w = W[c * 1024 + f];
#pragma unroll
        for (int r = 0; r < 64; r++) acc[r] = fmaf(sh[r][c], w, acc[r]);
    }
    float mx = acc[0];
#pragma unroll
    for (int r = 1; r < 64; r++) mx = fmaxf(mx, acc[r]);
    g_pmax[(b * 8 + rchunk) * 1024 + f] = mx + bias[f];
}

__global__ void final_reduce(float* __restrict__ gf) {
    int b = blockIdx.x, f = threadIdx.x;  // 1024
    float mx = g_pmax[(b * 8) * 1024 + f];
#pragma unroll
    for (int r = 1; r < 8; r++) mx = fmaxf(mx, g_pmax[(b * 8 + r) * 1024 + f]);
    gf[b * 1024 + f] = mx;
}

// ---------------- launch ---------------------------------------------------
extern "C" void kernel_launch(void* const* d_in, const int* in_sizes, int n_in,
                              void* d_out, int out_size) {
    const float* x     = (const float*)d_in[0];
    const float* zones = (const float*)d_in[1];
    const float* lf_W1 = (const float*)d_in[2];
    const float* lf_b1 = (const float*)d_in[3];
    const float* lf_W2 = (const float*)d_in[4];
    const float* lf_b2 = (const float*)d_in[5];
    const float* c1_W  = (const float*)d_in[6];
    const float* c1_b  = (const float*)d_in[7];
    const float* c2_W  = (const float*)d_in[8];
    const float* c2_b  = (const float*)d_in[9];
    const float* c3_W  = (const float*)d_in[10];
    const float* c3_b  = (const float*)d_in[11];

    float* lf_out = (float*)d_out;
    float* gf_out = (float*)d_out + (size_t)B_ * N_ * LF_;

    lf_kernel<<<(B_ * N_) / 32, 64>>>(x, lf_W1, lf_b1, lf_W2, lf_b2, lf_out);
    fps_kernel<1024, 4, N_, M1_, 0><<<B_, 1024>>>(x);       // FPS level 1
    p1_kernel<<<(B_ * N_) / 32, 64>>>(lf_out, zones, c1_W, c1_b);
    fps_kernel<512, 4, M1_, M2_, 1><<<B_, 512>>>(nullptr);  // FPS level 2
    sa1_kernel<<<dim3(M1_, B_), 128>>>(x, c1_W);
    p2_kernel<<<(B_ * M1_) / 32, 128>>>(c2_W, c2_b);
    sa2_kernel<<<dim3(M2_, B_), F2_>>>(c2_W);
    final_partial<<<dim3(8, 8, B_), 128>>>(c3_W, c3_b);
    final_reduce<<<B_, 1024>>>(gf_out);
}

// round 6
// speedup vs baseline: 1.8492x; 1.8492x over previous
#include <cuda_runtime.h>
#include <cuda_bf16.h>
#include <cstdint>

#define B_  4
#define N_  4096
#define M1_ 2048
#define M2_ 512
#define F1_ 64
#define F2_ 128
#define F3_ 1024
#define LF_ 64
#define MAXNBR 128

// ---------------- device scratch ----------------
__device__ float g_p1  [B_ * N_  * F1_];
__device__ float g_h1  [B_ * M1_ * F1_];
__device__ float g_ctr1[B_ * M1_ * 2];
__device__ float g_p2  [B_ * M1_ * F2_];
__device__ float g_h2  [B_ * M2_ * F2_];
__device__ float g_ctr2[B_ * M2_ * 2];
__device__ float g_pmax[B_ * 8 * F3_];

// ---------------- kernel: lf = tanh(tanh(x W1 + b1) W2 + b2) ----------
__global__ void lf_kernel(const float* __restrict__ x,
                          const float* __restrict__ W1, const float* __restrict__ b1,
                          const float* __restrict__ W2, const float* __restrict__ b2,
                          float* __restrict__ lf_out) {
    __shared__ float sW2[64 * 64];
    __shared__ float sW1[2 * 64];
    __shared__ float sb1[64], sb2[64];
    __shared__ float st1[64];
    int tid = threadIdx.x;
    for (int i = tid; i < 64 * 64; i += 64) sW2[i] = W2[i];
    sW1[tid] = W1[tid]; sW1[64 + tid] = W1[64 + tid];
    sb1[tid] = b1[tid]; sb2[tid] = b2[tid];
    __syncthreads();
    int row0 = blockIdx.x * 32;
    for (int r = 0; r < 32; r++) {
        int row = row0 + r;
        float x0 = x[row * 2], x1 = x[row * 2 + 1];
        float t1 = tanhf(x0 * sW1[tid] + x1 * sW1[64 + tid] + sb1[tid]);
        st1[tid] = t1;
        __syncthreads();
        float acc = sb2[tid];
#pragma unroll
        for (int c = 0; c < 64; c++) acc = fmaf(st1[c], sW2[c * 64 + tid], acc);
        lf_out[row * 64 + tid] = tanhf(acc);
        __syncthreads();
    }
}

// ---------------- p1[j] = [lf_j, zone_j] @ c1W[:65] + c1b ------
__global__ void p1_kernel(const float* __restrict__ lf, const float* __restrict__ zones,
                          const float* __restrict__ c1W, const float* __restrict__ c1b) {
    __shared__ float sW[65 * 64];
    __shared__ float sb[64];
    __shared__ float srow[64];
    int tid = threadIdx.x;  // 64
    for (int i = tid; i < 65 * 64; i += 64) sW[i] = c1W[i];
    sb[tid] = c1b[tid];
    __syncthreads();
    int row0 = blockIdx.x * 32;
    for (int r = 0; r < 32; r++) {
        int row = row0 + r;
        srow[tid] = lf[row * 64 + tid];
        __syncthreads();
        float z = zones[row];
        float acc = fmaf(z, sW[64 * 64 + tid], sb[tid]);
#pragma unroll
        for (int c = 0; c < 64; c++) acc = fmaf(srow[c], sW[c * 64 + tid], acc);
        g_p1[row * 64 + tid] = acc;
        __syncthreads();
    }
}

// ---------------- FPS: bucketed + warp bbox prune + redux merge (R4) ------
// Two-level reduction: warp redux -> lane0 STS.64 (double-buffered) ->
// barrier -> every warp redundantly reduces NW packed entries -> winner
// coords via one broadcast LDS from original-order table.
// Exact vs jnp.argmax: skipped warp updates are provably no-ops (bbox lower
// bound >= cached warp max); all reductions are (max value, min ORIGINAL
// index) -> identical first-occurrence winner.
template <int T, int P, int N, int M, int LEVEL>
__global__ __launch_bounds__(T, 1) void fps_kernel(const float* __restrict__ pos_in) {
    const int NW = T / 32;
    const unsigned FULL = 0xFFFFFFFFu;
    int b = blockIdx.x;
    int tid = threadIdx.x;
    int wid = tid >> 5, lane = tid & 31;
    const float2* p = (LEVEL == 0) ? (const float2*)(pos_in + (size_t)b * N * 2)
                                   : (const float2*)(g_ctr1 + (size_t)b * N * 2);
    float* cout = (LEVEL == 0) ? (g_ctr1 + (size_t)b * M * 2)
                               : (g_ctr2 + (size_t)b * M * 2);

    __shared__ float2 sxy[N];               // ORIGINAL order (winner lookup)
    __shared__ float spx[N], spy[N];        // sorted (init only)
    __shared__ unsigned short ssidx[N];     // sorted -> original idx
    __shared__ int counts[256], offs[256], cursor[256];
    __shared__ unsigned long long sVI[2][NW];

    // ---- load raw, publish original-order table ----
    float rx[P], ry[P];
    int cid[P];
#pragma unroll
    for (int k = 0; k < P; k++) {
        float2 v = p[tid + k * T];
        rx[k] = v.x; ry[k] = v.y;
        sxy[tid + k * T] = v;
    }
    if (tid < 256) counts[tid] = 0;
    __syncthreads();
#pragma unroll
    for (int k = 0; k < P; k++) {
        int cx = (int)fminf(fmaxf((rx[k] + 18.f) * (16.f / 36.f), 0.f), 15.f);
        int cy = (int)fminf(fmaxf((ry[k] + 18.f) * (16.f / 36.f), 0.f), 15.f);
        cid[k] = cy * 16 + cx;
        atomicAdd(&counts[cid[k]], 1);
    }
    __syncthreads();
    if (tid < 256) offs[tid] = counts[tid];
    __syncthreads();
    for (int d = 1; d < 256; d <<= 1) {
        int v = 0;
        if (tid < 256 && tid >= d) v = offs[tid - d];
        __syncthreads();
        if (tid < 256 && tid >= d) offs[tid] += v;
        __syncthreads();
    }
    if (tid < 256) cursor[tid] = offs[tid] - counts[tid];
    __syncthreads();
#pragma unroll
    for (int k = 0; k < P; k++) {
        int pos = atomicAdd(&cursor[cid[k]], 1);
        spx[pos] = rx[k]; spy[pos] = ry[k];
        ssidx[pos] = (unsigned short)(tid + k * T);
    }
    __syncthreads();

    // ---- registers: my sorted segment + warp bbox ----
    float px[P], py[P], md[P];
    unsigned sidx[P];
    float bx0 = 1e30f, bx1 = -1e30f, by0 = 1e30f, by1 = -1e30f;
    int base = tid * P;
#pragma unroll
    for (int k = 0; k < P; k++) {
        px[k] = spx[base + k]; py[k] = spy[base + k];
        sidx[k] = (unsigned)ssidx[base + k];
        md[k] = 1e10f;
        bx0 = fminf(bx0, px[k]); bx1 = fmaxf(bx1, px[k]);
        by0 = fminf(by0, py[k]); by1 = fmaxf(by1, py[k]);
    }
#pragma unroll
    for (int o = 16; o > 0; o >>= 1) {
        bx0 = fminf(bx0, __shfl_xor_sync(FULL, bx0, o));
        bx1 = fmaxf(bx1, __shfl_xor_sync(FULL, bx1, o));
        by0 = fminf(by0, __shfl_xor_sync(FULL, by0, o));
        by1 = fmaxf(by1, __shfl_xor_sync(FULL, by1, o));
    }
    __syncthreads();

    float2 c0 = sxy[0];
    float lx = c0.x, ly = c0.y;
    if (tid == 0) { cout[0] = lx; cout[1] = ly; }

    float wvf = 1e10f;          // cached warp max (uniform in warp)
    unsigned wi_ = 0u;          // cached warp argmin-idx among max

    for (int t = 1; t < M; t++) {
        float ex = fmaxf(fmaxf(bx0 - lx, lx - bx1), 0.f);
        float ey = fmaxf(fmaxf(by0 - ly, ly - by1), 0.f);
        float lb = fmaf(ex, ex, ey * ey);
        if (lb < wvf) {   // uniform per-warp branch (no divergence)
            float tb = -1.f;
#pragma unroll
            for (int k = 0; k < P; k++) {
                float dx = px[k] - lx, dy = py[k] - ly;
                float d2 = fmaf(dx, dx, dy * dy);
                md[k] = fminf(md[k], d2);
                tb = fmaxf(tb, md[k]);
            }
            unsigned bi = 0xFFFFFFFFu;
#pragma unroll
            for (int k = 0; k < P; k++)
                if (md[k] == tb && sidx[k] < bi) bi = sidx[k];
            unsigned vb = __float_as_uint(tb);
            unsigned wm = __reduce_max_sync(FULL, vb);
            unsigned cand = (vb == wm) ? bi : 0xFFFFFFFFu;
            wi_ = __reduce_min_sync(FULL, cand);
            wvf = __uint_as_float(wm);
        }
        int buf = t & 1;
        if (lane == 0)
            sVI[buf][wid] = ((unsigned long long)__float_as_uint(wvf) << 32) | wi_;
        __syncthreads();
        unsigned long long e;
        if (NW == 32) e = sVI[buf][lane];
        else          e = (lane < NW) ? sVI[buf][lane] : 0ull;
        unsigned v2 = (unsigned)(e >> 32), i2 = (unsigned)e;
        unsigned m2 = __reduce_max_sync(FULL, v2);
        unsigned c2 = (v2 == m2) ? i2 : 0xFFFFFFFFu;
        unsigned gi = __reduce_min_sync(FULL, c2);
        float2 w = sxy[gi];          // broadcast LDS.64
        lx = w.x; ly = w.y;
        if (tid == 0) { cout[t * 2] = lx; cout[t * 2 + 1] = ly; }
    }
}

// ---------------- SA1: radius scan + max-aggregate ------------------------
__global__ void sa1_kernel(const float* __restrict__ x, const float* __restrict__ c1W) {
    const int N = N_, M = M1_, F = F1_;
    int i = blockIdx.x, b = blockIdx.y, tid = threadIdx.x;  // 128 threads
    __shared__ float sdx[MAXNBR], sdy[MAXNBR];
    __shared__ int   snb[MAXNBR];
    __shared__ int   scnt;
    if (tid == 0) scnt = 0;
    __syncthreads();
    float cx = g_ctr1[(b * M + i) * 2], cy = g_ctr1[(b * M + i) * 2 + 1];
    const float2* pos = (const float2*)(x + (size_t)b * N * 2);
    for (int j = tid; j < N; j += 128) {
        float2 pj = pos[j];
        float dx = pj.x - cx, dy = pj.y - cy;
        float d2 = fmaf(dx, dx, dy * dy);
        if (d2 <= 0.25f) {
            int s = atomicAdd(&scnt, 1);
            if (s < MAXNBR) { snb[s] = j; sdx[s] = dx; sdy[s] = dy; }
        }
    }
    __syncthreads();
    if (tid >= F) return;
    int cnt = min(scnt, MAXNBR);
    float wx = c1W[65 * 64 + tid];
    float wy = c1W[66 * 64 + tid];
    float mx = -1e9f;
    const float* pb = g_p1 + (size_t)b * N * F;
    int n = 0;
    for (; n + 4 <= cnt; n += 4) {
        float v0 = pb[snb[n] * F + tid];
        float v1 = pb[snb[n + 1] * F + tid];
        float v2 = pb[snb[n + 2] * F + tid];
        float v3 = pb[snb[n + 3] * F + tid];
        float m0 = fmaf(sdx[n], wx, fmaf(sdy[n], wy, v0));
        float m1 = fmaf(sdx[n + 1], wx, fmaf(sdy[n + 1], wy, v1));
        float m2 = fmaf(sdx[n + 2], wx, fmaf(sdy[n + 2], wy, v2));
        float m3 = fmaf(sdx[n + 3], wx, fmaf(sdy[n + 3], wy, v3));
        mx = fmaxf(mx, fmaxf(fmaxf(m0, m1), fmaxf(m2, m3)));
    }
    for (; n < cnt; n++) {
        float m = fmaf(sdx[n], wx, fmaf(sdy[n], wy, pb[snb[n] * F + tid]));
        mx = fmaxf(mx, m);
    }
    g_h1[((size_t)b * M + i) * F + tid] = mx;
}

// ---------------- p2[j] = h1_j @ c2W[:64] + c2b ---------------------------
__global__ void p2_kernel(const float* __restrict__ c2W, const float* __restrict__ c2b) {
    __shared__ float sW[64 * 128];
    __shared__ float sb[128];
    __shared__ float srow[64];
    int tid = threadIdx.x;  // 128
    for (int i = tid; i < 64 * 128; i += 128) sW[i] = c2W[i];
    sb[tid] = c2b[tid];
    __syncthreads();
    int row0 = blockIdx.x * 32;
    for (int r = 0; r < 32; r++) {
        int row = row0 + r;
        if (tid < 64) srow[tid] = g_h1[row * 64 + tid];
        __syncthreads();
        float acc = sb[tid];
#pragma unroll
        for (int c = 0; c < 64; c++) acc = fmaf(srow[c], sW[c * 128 + tid], acc);
        g_p2[row * 128 + tid] = acc;
        __syncthreads();
    }
}

// ---------------- SA2 -----------------------------------------------------
__global__ void sa2_kernel(const float* __restrict__ c2W) {
    const int N = M1_, M = M2_, F = F2_;
    int i = blockIdx.x, b = blockIdx.y, tid = threadIdx.x;  // 128
    __shared__ float sdx[MAXNBR], sdy[MAXNBR];
    __shared__ int   snb[MAXNBR];
    __shared__ int   scnt;
    if (tid == 0) scnt = 0;
    __syncthreads();
    float cx = g_ctr2[(b * M + i) * 2], cy = g_ctr2[(b * M + i) * 2 + 1];
    const float2* pos = (const float2*)(g_ctr1 + (size_t)b * N * 2);
    for (int j = tid; j < N; j += F) {
        float2 pj = pos[j];
        float dx = pj.x - cx, dy = pj.y - cy;
        float d2 = fmaf(dx, dx, dy * dy);
        if (d2 <= 1.0f) {
            int s = atomicAdd(&scnt, 1);
            if (s < MAXNBR) { snb[s] = j; sdx[s] = dx; sdy[s] = dy; }
        }
    }
    __syncthreads();
    int cnt = min(scnt, MAXNBR);
    float wx = c2W[64 * 128 + tid];
    float wy = c2W[65 * 128 + tid];
    float mx = -1e9f;
    const float* pb = g_p2 + (size_t)b * N * F;
    int n = 0;
    for (; n + 4 <= cnt; n += 4) {
        float v0 = pb[snb[n] * F + tid];
        float v1 = pb[snb[n + 1] * F + tid];
        float v2 = pb[snb[n + 2] * F + tid];
        float v3 = pb[snb[n + 3] * F + tid];
        float m0 = fmaf(sdx[n], wx, fmaf(sdy[n], wy, v0));
        float m1 = fmaf(sdx[n + 1], wx, fmaf(sdy[n + 1], wy, v1));
        float m2 = fmaf(sdx[n + 2], wx, fmaf(sdy[n + 2], wy, v2));
        float m3 = fmaf(sdx[n + 3], wx, fmaf(sdy[n + 3], wy, v3));
        mx = fmaxf(mx, fmaxf(fmaxf(m0, m1), fmaxf(m2, m3)));
    }
    for (; n < cnt; n++) {
        float m = fmaf(sdx[n], wx, fmaf(sdy[n], wy, pb[snb[n] * F + tid]));
        mx = fmaxf(mx, m);
    }
    g_h2[((size_t)b * M + i) * F + tid] = mx;
}

// ---------------- final projection + partial max pool ---------------------
__global__ void final_partial(const float* __restrict__ W, const float* __restrict__ bias) {
    int fchunk = blockIdx.x, rchunk = blockIdx.y, b = blockIdx.z;
    int tid = threadIdx.x;  // 128
    int f = fchunk * 128 + tid;
    __shared__ float sh[64][132];
    int r0 = rchunk * 64;
    for (int e = tid; e < 64 * 130; e += 128) {
        int r = e / 130, c = e % 130;
        float v;
        if (c < 128) v = g_h2[((size_t)b * M2_ + r0 + r) * 128 + c];
        else         v = g_ctr2[(b * M2_ + r0 + r) * 2 + (c - 128)];
        sh[r][c] = v;
    }
    __syncthreads();
    float acc[64];
#pragma unroll
    for (int r = 0; r < 64; r++) acc[r] = 0.0f;
    for (int c = 0; c < 130; c++) {
        float w = W[c * 1024 + f];
#pragma unroll
        for (int r = 0; r < 64; r++) acc[r] = fmaf(sh[r][c], w, acc[r]);
    }
    float mx = acc[0];
#pragma unroll
    for (int r = 1; r < 64; r++) mx = fmaxf(mx, acc[r]);
    g_pmax[(b * 8 + rchunk) * 1024 + f] = mx + bias[f];
}

__global__ void final_reduce(float* __restrict__ gf) {
    int b = blockIdx.x, f = threadIdx.x;  // 1024
    float mx = g_pmax[(b * 8) * 1024 + f];
#pragma unroll
    for (int r = 1; r < 8; r++) mx = fmaxf(mx, g_pmax[(b * 8 + r) * 1024 + f]);
    gf[b * 1024 + f] = mx;
}

// ---------------- launch ---------------------------------------------------
extern "C" void kernel_launch(void* const* d_in, const int* in_sizes, int n_in,
                              void* d_out, int out_size) {
    const float* x     = (const float*)d_in[0];
    const float* zones = (const float*)d_in[1];
    const float* lf_W1 = (const float*)d_in[2];
    const float* lf_b1 = (const float*)d_in[3];
    const float* lf_W2 = (const float*)d_in[4];
    const float* lf_b2 = (const float*)d_in[5];
    const float* c1_W  = (const float*)d_in[6];
    const float* c1_b  = (const float*)d_in[7];
    const float* c2_W  = (const float*)d_in[8];
    const float* c2_b  = (const float*)d_in[9];
    const float* c3_W  = (const float*)d_in[10];
    const float* c3_b  = (const float*)d_in[11];

    float* lf_out = (float*)d_out;
    float* gf_out = (float*)d_out + (size_t)B_ * N_ * LF_;

    lf_kernel<<<(B_ * N_) / 32, 64>>>(x, lf_W1, lf_b1, lf_W2, lf_b2, lf_out);
    fps_kernel<1024, 4, N_, M1_, 0><<<B_, 1024>>>(x);       // FPS level 1
    p1_kernel<<<(B_ * N_) / 32, 64>>>(lf_out, zones, c1_W, c1_b);
    fps_kernel<512, 4, M1_, M2_, 1><<<B_, 512>>>(nullptr);  // FPS level 2
    sa1_kernel<<<dim3(M1_, B_), 128>>>(x, c1_W);
    p2_kernel<<<(B_ * M1_) / 32, 128>>>(c2_W, c2_b);
    sa2_kernel<<<dim3(M2_, B_), F2_>>>(c2_W);
    final_partial<<<dim3(8, 8, B_), 128>>>(c3_W, c3_b);
    final_reduce<<<B_, 1024>>>(gf_out);
}